// round 16
// baseline (speedup 1.0000x reference)
#include <cuda_runtime.h>
#include <cuda_bf16.h>
#include <math.h>
#include <float.h>

#define NB   4
#define NPTS 2048
#define KNN  20
#define CCAT 963

__device__ __forceinline__ float tf32r(float x){
    float r;
    asm("cvt.rna.tf32.f32 %0, %1;" : "=f"(r) : "f"(x));
    return r;
}

__device__ __forceinline__ void mma_tf32(float& c0, float& c1, float& c2, float& c3,
                                         unsigned a0, unsigned a1, unsigned a2, unsigned a3,
                                         unsigned b0, unsigned b1){
    asm volatile("mma.sync.aligned.m16n8k8.row.col.f32.tf32.tf32.f32 "
                 "{%0,%1,%2,%3}, {%4,%5,%6,%7}, {%8,%9}, {%0,%1,%2,%3};"
                 : "+f"(c0), "+f"(c1), "+f"(c2), "+f"(c3)
                 : "r"(a0), "r"(a1), "r"(a2), "r"(a3), "r"(b0), "r"(b1));
}

// ---------------- scratch (static device globals; no allocation) ----------------
__device__ float  g_xc[(size_t)NB*CCAT*NPTS];          // concat feature buffer (B,963,N)
__device__ float  g_dm[(size_t)NB*NPTS*NPTS];          // distance matrix; reused as h (B,2048,N)
__device__ int    g_knn[NB*NPTS*KNN];
__device__ float  g_w2[1024*256];                      // packed [Wd ; Wc-Wd]
__device__ float  g_ut[(size_t)NB*NPTS*1024];          // (B,N,2*Cout): u then t
__device__ float  g_ymax[(size_t)NB*NPTS*512];
__device__ float  g_ymin[(size_t)NB*NPTS*512];
__device__ float  g_sy [(size_t)NB*NPTS*512];
__device__ float  g_sy2[(size_t)NB*NPTS*512];
__device__ double g_chs[2048];
__device__ double g_chs2[2048];
__device__ float  g_scale[2048];
__device__ float  g_shift[2048];
__device__ float  g_bmax[NB*2048];
__device__ float  g_bmin[NB*2048];
__device__ float  g_p[NB*2048];
__device__ float  g_fc[NB*4096];
__device__ float  g_cat[NB*4096];
__device__ float  g_y7[NB*4096];

// ---------------- kernels ----------------

__global__ void copyx_kernel(const float* __restrict__ x, float* __restrict__ Xc){
    int idx = blockIdx.x*256 + threadIdx.x;
    if (idx >= NB*3*NPTS) return;
    int b = idx/(3*NPTS); int rem = idx%(3*NPTS);
    Xc[(size_t)b*CCAT*NPTS + rem] = x[idx];
}

__global__ void prepw2_kernel(const float* __restrict__ w, float* __restrict__ W2,
                              int Cin, int Cout){
    int idx = blockIdx.x*256 + threadIdx.x;
    int tot = 2*Cout*Cin;
    if (idx >= tot) return;
    int j = idx / Cin, c = idx % Cin;
    if (j < Cout) W2[idx] = w[(size_t)j*(2*Cin) + c];
    else {
        int jj = j - Cout;
        W2[idx] = w[(size_t)jj*(2*Cin) + Cin + c] - w[(size_t)jj*(2*Cin) + c];
    }
}

// D[b][n][m] = sum_c (X[c][n] - X[c][m])^2, symmetric: only upper-tri tile pairs.
// Inner math in packed f32x2 (bitwise identical per element: FADD(a,-b) == FSUB(a,b)).
#define DT 32   // number of 64-wide tiles (2048/64)
__global__ void dist_sym_kernel(const float* __restrict__ Xc, float* __restrict__ D,
                                int C, int coff){
    int b = blockIdx.z;
    int p = blockIdx.x;            // 0 .. DT*(DT+1)/2 - 1
    int bi = 0, accum = 0;
    while (p >= accum + (DT - bi)){ accum += DT - bi; bi++; }
    int bj = bi + (p - accum);
    int n0 = bi*64, m0 = bj*64;

    const float* Xb = Xc + ((size_t)b*CCAT + coff)*NPTS;
    __shared__ float As[16][64];
    __shared__ float Bs[16][64];   // stored NEGATED
    unsigned long long acc2[2][4];
    #pragma unroll
    for (int ip = 0; ip < 2; ip++)
        #pragma unroll
        for (int j = 0; j < 4; j++) acc2[ip][j] = 0ull;

    int t  = threadIdx.x;
    int tx = t & 15, ty = t >> 4;
    for (int c0 = 0; c0 < C; c0 += 16){
        #pragma unroll
        for (int r = 0; r < 4; r++){
            int lin = t + r*256;
            int kc = lin >> 6, i = lin & 63;
            float a = 0.f, bv = 0.f;
            if (c0+kc < C){
                a  = Xb[(size_t)(c0+kc)*NPTS + n0 + i];
                bv = Xb[(size_t)(c0+kc)*NPTS + m0 + i];
            }
            As[kc][i] = a; Bs[kc][i] = -bv;
        }
        __syncthreads();
        #pragma unroll
        for (int kc = 0; kc < 16; kc++){
            float4 aq = *reinterpret_cast<const float4*>(&As[kc][ty*4]);
            float4 bq = *reinterpret_cast<const float4*>(&Bs[kc][tx*4]);  // negated
            unsigned long long ap[2], bd[4];
            asm("mov.b64 %0,{%1,%2};" : "=l"(ap[0]) : "f"(aq.x), "f"(aq.y));
            asm("mov.b64 %0,{%1,%2};" : "=l"(ap[1]) : "f"(aq.z), "f"(aq.w));
            asm("mov.b64 %0,{%1,%1};" : "=l"(bd[0]) : "f"(bq.x));
            asm("mov.b64 %0,{%1,%1};" : "=l"(bd[1]) : "f"(bq.y));
            asm("mov.b64 %0,{%1,%1};" : "=l"(bd[2]) : "f"(bq.z));
            asm("mov.b64 %0,{%1,%1};" : "=l"(bd[3]) : "f"(bq.w));
            #pragma unroll
            for (int ip = 0; ip < 2; ip++)
                #pragma unroll
                for (int j = 0; j < 4; j++){
                    unsigned long long d;
                    asm("add.rn.f32x2 %0, %1, %2;" : "=l"(d) : "l"(ap[ip]), "l"(bd[j]));
                    asm("fma.rn.f32x2 %0, %1, %2, %3;"
                        : "=l"(acc2[ip][j]) : "l"(d), "l"(d), "l"(acc2[ip][j]));
                }
        }
        __syncthreads();
    }
    float accs[4][4];
    #pragma unroll
    for (int ip = 0; ip < 2; ip++)
        #pragma unroll
        for (int j = 0; j < 4; j++)
            asm("mov.b64 {%0,%1}, %2;"
                : "=f"(accs[2*ip][j]), "=f"(accs[2*ip+1][j]) : "l"(acc2[ip][j]));

    float* Db = D + (size_t)b*NPTS*NPTS;
    #pragma unroll
    for (int i = 0; i < 4; i++){
        int n = n0 + ty*4 + i;
        float4 o;
        o.x = accs[i][0]; o.y = accs[i][1]; o.z = accs[i][2]; o.w = accs[i][3];
        *reinterpret_cast<float4*>(&Db[(size_t)n*NPTS + m0 + tx*4]) = o;
    }
    if (bi != bj){
        #pragma unroll
        for (int j = 0; j < 4; j++){
            int m = m0 + tx*4 + j;
            float4 o;
            o.x = accs[0][j]; o.y = accs[1][j]; o.z = accs[2][j]; o.w = accs[3][j];
            *reinterpret_cast<float4*>(&Db[(size_t)m*NPTS + n0 + ty*4]) = o;
        }
    }
}

// Radix-select top-KNN smallest per row (exact; ties -> lowest index).
// Histogram adds are warp-aggregated via match_any (bins cluster heavily).
__global__ void topk_kernel(const float* __restrict__ D, int* __restrict__ IDX){
    int b = blockIdx.y, n = blockIdx.x;
    const float* row = D + ((size_t)b*NPTS + n)*NPTS;
    int t = threadIdx.x;
    int lane = t & 31;

    unsigned v[8];
    #pragma unroll
    for (int j = 0; j < 8; j++)
        v[j] = __float_as_uint(row[t + j*256]);

    __shared__ unsigned hist[256];
    __shared__ unsigned scn[256];
    __shared__ unsigned sh_digit, sh_cntless;
    __shared__ int      outpos, eqcnt;
    __shared__ int      eqlist[2048];

    unsigned prefix = 0;
    int r = KNN;

    #pragma unroll
    for (int pass = 0; pass < 4; pass++){
        int shift = 24 - pass*8;
        hist[t] = 0;
        __syncthreads();
        #pragma unroll
        for (int j = 0; j < 8; j++){
            unsigned x = v[j];
            bool alive = (pass == 0) || ((x >> (shift+8)) == (prefix >> (shift+8)));
            unsigned digit = (x >> shift) & 0xFF;
            unsigned key = alive ? digit : (0x100u | (unsigned)lane);
            unsigned mask = __match_any_sync(0xFFFFFFFFu, key);
            if (alive && lane == (__ffs(mask) - 1))
                atomicAdd(&hist[digit], (unsigned)__popc(mask));
        }
        __syncthreads();
        scn[t] = hist[t];
        __syncthreads();
        for (int off = 1; off < 256; off <<= 1){
            unsigned a = (t >= off) ? scn[t-off] : 0u;
            __syncthreads();
            scn[t] += a;
            __syncthreads();
        }
        unsigned prev = (t == 0) ? 0u : scn[t-1];
        if (scn[t] >= (unsigned)r && prev < (unsigned)r){
            sh_digit = (unsigned)t;
            sh_cntless = prev;
        }
        __syncthreads();
        prefix |= sh_digit << shift;
        r -= (int)sh_cntless;
        __syncthreads();
    }

    unsigned T = prefix;
    if (t == 0){ outpos = 0; eqcnt = 0; }
    __syncthreads();

    int base = ((size_t)b*NPTS + n)*KNN;
    #pragma unroll
    for (int j = 0; j < 8; j++){
        unsigned x = v[j];
        int idx = t + j*256;
        if (x < T){
            int p = atomicAdd(&outpos, 1);
            IDX[base + p] = idx;
        } else if (x == T){
            int p = atomicAdd(&eqcnt, 1);
            eqlist[p] = idx;
        }
    }
    __syncthreads();

    if (t < 32){
        int start = KNN - r;
        int ec = eqcnt;
        for (int it = 0; it < r; it++){
            int best = 0x7FFFFFFF;
            for (int i = t; i < ec; i += 32) best = min(best, eqlist[i]);
            #pragma unroll
            for (int o = 16; o > 0; o >>= 1)
                best = min(best, __shfl_xor_sync(0xFFFFFFFF, best, o));
            if (t == 0) IDX[base + start + it] = best;
            for (int i = t; i < ec; i += 32)
                if (eqlist[i] == best) eqlist[i] = 0x7FFFFFFF;
            __syncwarp();
        }
    }
}

// UT[b][n][j] = sum_c W2[j][c] * X[b][c][n]  (exact fp32; layers 1-3 — feeds kNN)
__global__ void gemm_ut_kernel(const float* __restrict__ Xc, const float* __restrict__ W2,
                               float* __restrict__ UT, int Cin, int J2, int coff){
    int b  = blockIdx.z;
    int n0 = blockIdx.y*64, j0 = blockIdx.x*64;
    const float* Xb = Xc + ((size_t)b*CCAT + coff)*NPTS;
    __shared__ float Xs[16][64];
    __shared__ float Ws[16][64];
    float acc[4][4] = {};
    int t = threadIdx.x;
    int tx = t & 15, ty = t >> 4;
    for (int c0 = 0; c0 < Cin; c0 += 16){
        #pragma unroll
        for (int r = 0; r < 4; r++){
            int lin = t + r*256;
            int kc = lin >> 6, i = lin & 63;
            Xs[kc][i] = (c0+kc < Cin) ? Xb[(size_t)(c0+kc)*NPTS + n0 + i] : 0.f;
            int j = lin >> 4, kc2 = lin & 15;
            Ws[kc2][j] = (c0+kc2 < Cin) ? W2[(size_t)(j0+j)*Cin + c0 + kc2] : 0.f;
        }
        __syncthreads();
        #pragma unroll
        for (int kc = 0; kc < 16; kc++){
            float av[4], wv[4];
            #pragma unroll
            for (int i = 0; i < 4; i++){ av[i] = Xs[kc][ty*4+i]; wv[i] = Ws[kc][tx*4+i]; }
            #pragma unroll
            for (int i = 0; i < 4; i++)
                #pragma unroll
                for (int j = 0; j < 4; j++)
                    acc[i][j] += av[i]*wv[j];
        }
        __syncthreads();
    }
    #pragma unroll
    for (int i = 0; i < 4; i++){
        int n = n0 + ty*4 + i;
        float4 o; o.x = acc[i][0]; o.y = acc[i][1]; o.z = acc[i][2]; o.w = acc[i][3];
        *reinterpret_cast<float4*>(&UT[((size_t)b*NPTS + n)*J2 + j0 + tx*4]) = o;
    }
}

// Layer-4 UT via 3xTF32 tensor cores (near-fp32 accuracy).
__global__ void gemm_ut4_mma_kernel(const float* __restrict__ Xc, const float* __restrict__ W2,
                                    float* __restrict__ UT){
    const int Cin = 256, J2 = 1024, coff = 195;
    int b  = blockIdx.z;
    int j0 = blockIdx.x*128, n0 = blockIdx.y*128;
    const float* Xb = Xc + ((size_t)b*CCAT + coff)*NPTS;
    __shared__ float Ahi[128][17], Alo[128][17];   // [n][k]
    __shared__ float Bhi[16][133], Blo[16][133];   // [k][j]
    int t = threadIdx.x;
    int warp = t >> 5, lane = t & 31;
    int g = lane >> 2, tg = lane & 3;
    float acc[4][4][4];
    #pragma unroll
    for (int i=0;i<4;i++)
        #pragma unroll
        for (int j=0;j<4;j++)
            #pragma unroll
            for (int r=0;r<4;r++) acc[i][j][r]=0.f;

    for (int c0 = 0; c0 < Cin; c0 += 16){
        #pragma unroll
        for (int r = 0; r < 8; r++){           // A: 128 n x 16 k
            int lin = t + r*256;
            int k = lin >> 7, i = lin & 127;
            float v = Xb[(size_t)(c0+k)*NPTS + n0 + i];
            float hi = tf32r(v);
            Ahi[i][k] = hi; Alo[i][k] = tf32r(v - hi);
        }
        #pragma unroll
        for (int r = 0; r < 8; r++){           // B: 16 k x 128 j
            int lin = t + r*256;
            int j = lin >> 4, k = lin & 15;
            float v = W2[(size_t)(j0+j)*Cin + c0 + k];
            float hi = tf32r(v);
            Bhi[k][j] = hi; Blo[k][j] = tf32r(v - hi);
        }
        __syncthreads();
        #pragma unroll
        for (int ks = 0; ks < 16; ks += 8){
            unsigned ah[4][4], al[4][4], bh[4][2], bl[4][2];
            #pragma unroll
            for (int i = 0; i < 4; i++){
                int nm = (warp & 1)*64 + i*16;
                ah[i][0] = __float_as_uint(Ahi[nm+g   ][ks+tg  ]);
                ah[i][1] = __float_as_uint(Ahi[nm+g+8 ][ks+tg  ]);
                ah[i][2] = __float_as_uint(Ahi[nm+g   ][ks+tg+4]);
                ah[i][3] = __float_as_uint(Ahi[nm+g+8 ][ks+tg+4]);
                al[i][0] = __float_as_uint(Alo[nm+g   ][ks+tg  ]);
                al[i][1] = __float_as_uint(Alo[nm+g+8 ][ks+tg  ]);
                al[i][2] = __float_as_uint(Alo[nm+g   ][ks+tg+4]);
                al[i][3] = __float_as_uint(Alo[nm+g+8 ][ks+tg+4]);
            }
            #pragma unroll
            for (int j = 0; j < 4; j++){
                int jm = (warp >> 1)*32 + j*8;
                bh[j][0] = __float_as_uint(Bhi[ks+tg  ][jm+g]);
                bh[j][1] = __float_as_uint(Bhi[ks+tg+4][jm+g]);
                bl[j][0] = __float_as_uint(Blo[ks+tg  ][jm+g]);
                bl[j][1] = __float_as_uint(Blo[ks+tg+4][jm+g]);
            }
            #pragma unroll
            for (int i = 0; i < 4; i++)
                #pragma unroll
                for (int j = 0; j < 4; j++){
                    mma_tf32(acc[i][j][0],acc[i][j][1],acc[i][j][2],acc[i][j][3],
                             al[i][0],al[i][1],al[i][2],al[i][3],bh[j][0],bh[j][1]);
                    mma_tf32(acc[i][j][0],acc[i][j][1],acc[i][j][2],acc[i][j][3],
                             ah[i][0],ah[i][1],ah[i][2],ah[i][3],bl[j][0],bl[j][1]);
                    mma_tf32(acc[i][j][0],acc[i][j][1],acc[i][j][2],acc[i][j][3],
                             ah[i][0],ah[i][1],ah[i][2],ah[i][3],bh[j][0],bh[j][1]);
                }
        }
        __syncthreads();
    }
    int wn = n0 + (warp & 1)*64;
    int wj = j0 + (warp >> 1)*32;
    #pragma unroll
    for (int i = 0; i < 4; i++){
        int nrow = wn + i*16;
        #pragma unroll
        for (int j = 0; j < 4; j++){
            int jcol = wj + j*8 + 2*tg;
            float2 v0 = make_float2(acc[i][j][0], acc[i][j][1]);
            float2 v1 = make_float2(acc[i][j][2], acc[i][j][3]);
            *reinterpret_cast<float2*>(&UT[((size_t)b*NPTS + nrow + g    )*J2 + jcol]) = v0;
            *reinterpret_cast<float2*>(&UT[((size_t)b*NPTS + nrow + g + 8)*J2 + jcol]) = v1;
        }
    }
}

// w5 GEMM via 3xTF32 tensor cores: Out[b][o][n] = sum_c W[o][c] * X[b][c][n]
__global__ void gemm_wx_mma_kernel(const float* __restrict__ W, const float* __restrict__ Xc,
                                   float* __restrict__ Out){
    const int C = CCAT, O = 2048;
    int b  = blockIdx.z;
    int o0 = blockIdx.y*128, n0 = blockIdx.x*128;
    const float* Xb = Xc + (size_t)b*CCAT*NPTS;
    __shared__ float Whi[128][17], Wlo[128][17];   // [o][k]
    __shared__ float Xhi[16][132], Xlo[16][132];   // [k][n]
    int t = threadIdx.x;
    int warp = t >> 5, lane = t & 31;
    int g = lane >> 2, tg = lane & 3;
    float acc[4][4][4];
    #pragma unroll
    for (int i=0;i<4;i++)
        #pragma unroll
        for (int j=0;j<4;j++)
            #pragma unroll
            for (int r=0;r<4;r++) acc[i][j][r]=0.f;

    for (int c0 = 0; c0 < C; c0 += 16){
        #pragma unroll
        for (int r = 0; r < 8; r++){           // W: 128 o x 16 k (scalar; stride 963)
            int lin = t + r*256;
            int o = lin >> 4, k = lin & 15;
            float v = (c0+k < C) ? W[(size_t)(o0+o)*C + c0 + k] : 0.f;
            float hi = tf32r(v);
            Whi[o][k] = hi; Wlo[o][k] = tf32r(v - hi);
        }
        #pragma unroll
        for (int r = 0; r < 2; r++){           // X: 16 k x 128 n via float4
            int lin = t + r*256;
            int k = lin >> 5, nq = lin & 31;
            float4 v = make_float4(0.f,0.f,0.f,0.f);
            if (c0+k < C)
                v = *reinterpret_cast<const float4*>(&Xb[(size_t)(c0+k)*NPTS + n0 + nq*4]);
            float4 h, l;
            h.x = tf32r(v.x); l.x = tf32r(v.x - h.x);
            h.y = tf32r(v.y); l.y = tf32r(v.y - h.y);
            h.z = tf32r(v.z); l.z = tf32r(v.z - h.z);
            h.w = tf32r(v.w); l.w = tf32r(v.w - h.w);
            *reinterpret_cast<float4*>(&Xhi[k][nq*4]) = h;
            *reinterpret_cast<float4*>(&Xlo[k][nq*4]) = l;
        }
        __syncthreads();
        #pragma unroll
        for (int ks = 0; ks < 16; ks += 8){
            unsigned ah[4][4], al[4][4], bh[4][2], bl[4][2];
            #pragma unroll
            for (int i = 0; i < 4; i++){
                int om = (warp & 1)*64 + i*16;
                ah[i][0] = __float_as_uint(Whi[om+g   ][ks+tg  ]);
                ah[i][1] = __float_as_uint(Whi[om+g+8 ][ks+tg  ]);
                ah[i][2] = __float_as_uint(Whi[om+g   ][ks+tg+4]);
                ah[i][3] = __float_as_uint(Whi[om+g+8 ][ks+tg+4]);
                al[i][0] = __float_as_uint(Wlo[om+g   ][ks+tg  ]);
                al[i][1] = __float_as_uint(Wlo[om+g+8 ][ks+tg  ]);
                al[i][2] = __float_as_uint(Wlo[om+g   ][ks+tg+4]);
                al[i][3] = __float_as_uint(Wlo[om+g+8 ][ks+tg+4]);
            }
            #pragma unroll
            for (int j = 0; j < 4; j++){
                int nm = (warp >> 1)*32 + j*8;
                bh[j][0] = __float_as_uint(Xhi[ks+tg  ][nm+g]);
                bh[j][1] = __float_as_uint(Xhi[ks+tg+4][nm+g]);
                bl[j][0] = __float_as_uint(Xlo[ks+tg  ][nm+g]);
                bl[j][1] = __float_as_uint(Xlo[ks+tg+4][nm+g]);
            }
            #pragma unroll
            for (int i = 0; i < 4; i++)
                #pragma unroll
                for (int j = 0; j < 4; j++){
                    mma_tf32(acc[i][j][0],acc[i][j][1],acc[i][j][2],acc[i][j][3],
                             al[i][0],al[i][1],al[i][2],al[i][3],bh[j][0],bh[j][1]);
                    mma_tf32(acc[i][j][0],acc[i][j][1],acc[i][j][2],acc[i][j][3],
                             ah[i][0],ah[i][1],ah[i][2],ah[i][3],bl[j][0],bl[j][1]);
                    mma_tf32(acc[i][j][0],acc[i][j][1],acc[i][j][2],acc[i][j][3],
                             ah[i][0],ah[i][1],ah[i][2],ah[i][3],bh[j][0],bh[j][1]);
                }
        }
        __syncthreads();
    }
    int wo = o0 + (warp & 1)*64;
    int wn = n0 + (warp >> 1)*32;
    #pragma unroll
    for (int i = 0; i < 4; i++){
        int orow = wo + i*16;
        #pragma unroll
        for (int j = 0; j < 4; j++){
            int ncol = wn + j*8 + 2*tg;
            float2 v0 = make_float2(acc[i][j][0], acc[i][j][1]);
            float2 v1 = make_float2(acc[i][j][2], acc[i][j][3]);
            *reinterpret_cast<float2*>(&Out[((size_t)b*O + orow + g    )*NPTS + ncol]) = v0;
            *reinterpret_cast<float2*>(&Out[((size_t)b*O + orow + g + 8)*NPTS + ncol]) = v1;
        }
    }
}

// Gather: one warp per point, float4 channel strides. 8 points per 256-thread block.
__global__ void gather_kernel(const float* __restrict__ UT, const int* __restrict__ IDX,
                              float* __restrict__ YMAX, float* __restrict__ YMIN,
                              float* __restrict__ SY, float* __restrict__ SY2,
                              int Cout, int J2){
    int b = blockIdx.y;
    int n0 = blockIdx.x*8;
    int t = threadIdx.x;
    int w = t >> 5, lane = t & 31;
    int n = n0 + w;
    __shared__ int midx[8][KNN];
    if (t < 8*KNN) midx[t/KNN][t%KNN] = IDX[((size_t)b*NPTS + n0 + t/KNN)*KNN + t%KNN];
    __syncthreads();
    const float* utb = UT + (size_t)b*NPTS*J2;
    const float* tr  = utb + (size_t)n*J2 + Cout;
    int nq = Cout >> 2;
    for (int o4 = lane; o4 < nq; o4 += 32){
        int o = o4*4;
        float4 tv = *reinterpret_cast<const float4*>(tr + o);
        float4 mx = make_float4(-FLT_MAX,-FLT_MAX,-FLT_MAX,-FLT_MAX);
        float4 mn = make_float4( FLT_MAX, FLT_MAX, FLT_MAX, FLT_MAX);
        float4 s  = make_float4(0.f,0.f,0.f,0.f);
        float4 s2 = make_float4(0.f,0.f,0.f,0.f);
        #pragma unroll
        for (int k = 0; k < KNN; k++){
            float4 u = *reinterpret_cast<const float4*>(&utb[(size_t)midx[w][k]*J2 + o]);
            float4 y;
            y.x = u.x + tv.x; y.y = u.y + tv.y; y.z = u.z + tv.z; y.w = u.w + tv.w;
            mx.x = fmaxf(mx.x, y.x); mx.y = fmaxf(mx.y, y.y);
            mx.z = fmaxf(mx.z, y.z); mx.w = fmaxf(mx.w, y.w);
            mn.x = fminf(mn.x, y.x); mn.y = fminf(mn.y, y.y);
            mn.z = fminf(mn.z, y.z); mn.w = fminf(mn.w, y.w);
            s.x += y.x; s.y += y.y; s.z += y.z; s.w += y.w;
            s2.x += y.x*y.x; s2.y += y.y*y.y; s2.z += y.z*y.z; s2.w += y.w*y.w;
        }
        size_t oi = ((size_t)(b*NPTS + n))*Cout + o;
        *reinterpret_cast<float4*>(&YMAX[oi]) = mx;
        *reinterpret_cast<float4*>(&YMIN[oi]) = mn;
        *reinterpret_cast<float4*>(&SY[oi])   = s;
        *reinterpret_cast<float4*>(&SY2[oi])  = s2;
    }
}

__global__ void colsum_kernel(const float* __restrict__ SY, const float* __restrict__ SY2,
                              double* __restrict__ CHS, double* __restrict__ CHS2, int Cout){
    int o  = blockIdx.x*256 + threadIdx.x;
    int r0 = blockIdx.y*64;
    if (o >= Cout) return;
    double a = 0.0, a2 = 0.0;
    for (int r = 0; r < 64; r++){
        size_t idx = (size_t)(r0 + r)*Cout + o;
        a += (double)SY[idx]; a2 += (double)SY2[idx];
    }
    atomicAdd(&CHS[o], a);
    atomicAdd(&CHS2[o], a2);
}

__global__ void bnstats_kernel(const double* __restrict__ CHS, const double* __restrict__ CHS2,
                               const float* __restrict__ g, const float* __restrict__ beta,
                               float* __restrict__ scale, float* __restrict__ shift,
                               int C, double invcnt){
    int o = blockIdx.x*256 + threadIdx.x;
    if (o >= C) return;
    double m   = CHS[o]*invcnt;
    double var = CHS2[o]*invcnt - m*m;
    float r   = rsqrtf((float)var + 1e-5f);
    float sc  = g[o]*r;
    scale[o] = sc;
    shift[o] = beta[o] - (float)m*sc;
}

// out = max(f(ymax), f(ymin)), f = lrelu(v*scale+shift); write transposed to (B,C,N)
__global__ void finalize_kernel(const float* __restrict__ YMAX, const float* __restrict__ YMIN,
                                const float* __restrict__ scale, const float* __restrict__ shift,
                                float* __restrict__ Xc, int Cout, int coff){
    int b  = blockIdx.z;
    int n0 = blockIdx.x*32, o0 = blockIdx.y*32;
    __shared__ float s[32][33];
    int tx = threadIdx.x, ty = threadIdx.y;   // 32 x 8
    #pragma unroll
    for (int i = 0; i < 4; i++){
        int n = n0 + ty + i*8, o = o0 + tx;
        size_t idx = ((size_t)(b*NPTS + n))*Cout + o;
        float sc = scale[o], sh = shift[o];
        float v1 = YMAX[idx]*sc + sh; v1 = v1 > 0.f ? v1 : 0.2f*v1;
        float v2 = YMIN[idx]*sc + sh; v2 = v2 > 0.f ? v2 : 0.2f*v2;
        s[tx][ty + i*8] = fmaxf(v1, v2);
    }
    __syncthreads();
    #pragma unroll
    for (int i = 0; i < 4; i++){
        int o = o0 + ty + i*8, n = n0 + tx;
        Xc[((size_t)b*CCAT + coff + o)*NPTS + n] = s[ty + i*8][tx];
    }
}

// per (b,o): sum/sumsq/max/min over n of h  (double accumulation)
__global__ void hstats_kernel(const float* __restrict__ H, double* __restrict__ CHS,
                              double* __restrict__ CHS2, float* __restrict__ BMAX,
                              float* __restrict__ BMIN){
    int b = blockIdx.y, o = blockIdx.x;
    const float* row = H + ((size_t)b*2048 + o)*NPTS;
    int t = threadIdx.x;
    double s = 0.0, s2 = 0.0;
    float mx = -FLT_MAX, mn = FLT_MAX;
    for (int i = t; i < NPTS; i += 256){
        float v = row[i];
        s += (double)v; s2 += (double)v*(double)v;
        mx = fmaxf(mx, v); mn = fminf(mn, v);
    }
    __shared__ double rs[256], rs2[256];
    __shared__ float rmx[256], rmn[256];
    rs[t] = s; rs2[t] = s2; rmx[t] = mx; rmn[t] = mn;
    __syncthreads();
    for (int st = 128; st > 0; st >>= 1){
        if (t < st){
            rs[t] += rs[t+st]; rs2[t] += rs2[t+st];
            rmx[t] = fmaxf(rmx[t], rmx[t+st]); rmn[t] = fminf(rmn[t], rmn[t+st]);
        }
        __syncthreads();
    }
    if (t == 0){
        atomicAdd(&CHS[o], rs[0]);
        atomicAdd(&CHS2[o], rs2[0]);
        BMAX[b*2048 + o] = rmx[0];
        BMIN[b*2048 + o] = rmn[0];
    }
}

__global__ void p_kernel(const double* __restrict__ CHS, const double* __restrict__ CHS2,
                         const float* __restrict__ g5, const float* __restrict__ b5,
                         const float* __restrict__ BMAX, const float* __restrict__ BMIN,
                         float* __restrict__ P, float* __restrict__ CAT){
    int o = blockIdx.x*256 + threadIdx.x;
    if (o >= 2048) return;
    double invcnt = 1.0/((double)NB*NPTS);
    double m = CHS[o]*invcnt;
    double var = CHS2[o]*invcnt - m*m;
    float sc = g5[o]*rsqrtf((float)var + 1e-5f);
    float sh = b5[o] - (float)m*sc;
    for (int b = 0; b < NB; b++){
        float v1 = BMAX[b*2048+o]*sc + sh; v1 = v1 > 0.f ? v1 : 0.2f*v1;
        float v2 = BMIN[b*2048+o]*sc + sh; v2 = v2 > 0.f ? v2 : 0.2f*v2;
        float v = fmaxf(v1, v2);
        P[b*2048 + o] = v;
        CAT[b*4096 + 2048 + o] = v;
    }
}

// OUT[b][o] = sum_c W[o][c]*IN[b][c] + bias[o], optional tanh
__global__ void fc_kernel(const float* __restrict__ W, const float* __restrict__ bias,
                          const float* __restrict__ IN, float* __restrict__ OUT,
                          int Cin, int O, int do_tanh){
    int o = blockIdx.x, t = threadIdx.x;
    const float* wr = W + (size_t)o*Cin;
    float a0 = 0.f, a1 = 0.f, a2 = 0.f, a3 = 0.f;
    for (int c = t; c < Cin; c += 256){
        float wv = wr[c];
        a0 += wv*IN[c];
        a1 += wv*IN[Cin + c];
        a2 += wv*IN[2*Cin + c];
        a3 += wv*IN[3*Cin + c];
    }
    __shared__ float red[4][256];
    red[0][t] = a0; red[1][t] = a1; red[2][t] = a2; red[3][t] = a3;
    __syncthreads();
    for (int s = 128; s > 0; s >>= 1){
        if (t < s){
            red[0][t] += red[0][t+s]; red[1][t] += red[1][t+s];
            red[2][t] += red[2][t+s]; red[3][t] += red[3][t+s];
        }
        __syncthreads();
    }
    if (t == 0){
        float bv = bias[o];
        for (int b = 0; b < NB; b++){
            float v = red[b][0] + bv;
            if (do_tanh) v = tanhf(v);
            OUT[(size_t)b*O + o] = v;
        }
    }
}

// batch-of-4 BN + relu (L=1 case)
__global__ void bnrelu4_kernel(const float* __restrict__ Y, const float* __restrict__ g,
                               const float* __restrict__ beta, float* __restrict__ OUT,
                               int C, int outStride, int outOff){
    int o = blockIdx.x*256 + threadIdx.x;
    if (o >= C) return;
    float m = 0.f;
    #pragma unroll
    for (int b = 0; b < NB; b++) m += Y[(size_t)b*C + o];
    m *= 0.25f;
    float var = 0.f;
    #pragma unroll
    for (int b = 0; b < NB; b++){ float d = Y[(size_t)b*C + o] - m; var += d*d; }
    var *= 0.25f;
    float sc = g[o]*rsqrtf(var + 1e-5f);
    float sh = beta[o] - m*sc;
    #pragma unroll
    for (int b = 0; b < NB; b++){
        float v = Y[(size_t)b*C + o]*sc + sh;
        OUT[(size_t)b*outStride + outOff + o] = fmaxf(v, 0.f);
    }
}

// ---------------- host orchestration ----------------
extern "C" void kernel_launch(void* const* d_in, const int* in_sizes, int n_in,
                              void* d_out, int out_size){
    (void)in_sizes; (void)n_in; (void)out_size;
    const float* x   = (const float*)d_in[0];
    const float* w5  = (const float*)d_in[13];
    const float* g5  = (const float*)d_in[14];
    const float* b5  = (const float*)d_in[15];
    const float* w6  = (const float*)d_in[16];
    const float* wb6 = (const float*)d_in[17];
    const float* g6  = (const float*)d_in[18];
    const float* b6  = (const float*)d_in[19];
    const float* w7  = (const float*)d_in[20];
    const float* wb7 = (const float*)d_in[21];
    const float* g7  = (const float*)d_in[22];
    const float* b7  = (const float*)d_in[23];
    const float* w8  = (const float*)d_in[24];
    const float* wb8 = (const float*)d_in[25];

    void *p_xc, *p_dm, *p_knn, *p_w2, *p_ut, *p_ymax, *p_ymin, *p_sy, *p_sy2;
    void *p_chs, *p_chs2, *p_scale, *p_shift, *p_bmax, *p_bmin, *p_p, *p_fc, *p_cat, *p_y7;
    cudaGetSymbolAddress(&p_xc, g_xc);
    cudaGetSymbolAddress(&p_dm, g_dm);       cudaGetSymbolAddress(&p_knn, g_knn);
    cudaGetSymbolAddress(&p_w2, g_w2);       cudaGetSymbolAddress(&p_ut, g_ut);
    cudaGetSymbolAddress(&p_ymax, g_ymax);   cudaGetSymbolAddress(&p_ymin, g_ymin);
    cudaGetSymbolAddress(&p_sy, g_sy);       cudaGetSymbolAddress(&p_sy2, g_sy2);
    cudaGetSymbolAddress(&p_chs, g_chs);     cudaGetSymbolAddress(&p_chs2, g_chs2);
    cudaGetSymbolAddress(&p_scale, g_scale); cudaGetSymbolAddress(&p_shift, g_shift);
    cudaGetSymbolAddress(&p_bmax, g_bmax);   cudaGetSymbolAddress(&p_bmin, g_bmin);
    cudaGetSymbolAddress(&p_p, g_p);         cudaGetSymbolAddress(&p_fc, g_fc);
    cudaGetSymbolAddress(&p_cat, g_cat);     cudaGetSymbolAddress(&p_y7, g_y7);

    float* xc  = (float*)p_xc;
    float* dm  = (float*)p_dm;   int*   kn  = (int*)p_knn;
    float* W2  = (float*)p_w2;   float* ut  = (float*)p_ut;
    float* ymx = (float*)p_ymax; float* ymn = (float*)p_ymin;
    float* sy  = (float*)p_sy;   float* sy2 = (float*)p_sy2;
    double* chs = (double*)p_chs;double* chs2= (double*)p_chs2;
    float* scl = (float*)p_scale;float* shf = (float*)p_shift;
    float* bmx = (float*)p_bmax; float* bmn = (float*)p_bmin;
    float* pp  = (float*)p_p;    float* fc  = (float*)p_fc;
    float* cat = (float*)p_cat;  float* y7  = (float*)p_y7;

    copyx_kernel<<<(NB*3*NPTS + 255)/256, 256>>>(x, xc);

    struct LCfg { int cin, cout, offin, offout, wi, gi, bi; };
    const LCfg L[4] = {
        {  3,  64,   0,   3,  1,  2,  3},
        { 64, 128,   3,  67,  4,  5,  6},
        {128, 256,  67, 195,  7,  8,  9},
        {256, 512, 195, 451, 10, 11, 12},
    };

    const int NPAIR = DT*(DT+1)/2;   // 528

    for (int l = 0; l < 4; l++){
        const float* w  = (const float*)d_in[L[l].wi];
        const float* gg = (const float*)d_in[L[l].gi];
        const float* bb = (const float*)d_in[L[l].bi];
        int Cin = L[l].cin, Cout = L[l].cout, J2 = 2*Cout;

        prepw2_kernel<<<(2*Cout*Cin + 255)/256, 256>>>(w, W2, Cin, Cout);
        dist_sym_kernel<<<dim3(NPAIR, 1, NB), 256>>>(xc, dm, Cin, L[l].offin);
        topk_kernel<<<dim3(NPTS, NB), 256>>>(dm, kn);
        if (l == 3){
            gemm_ut4_mma_kernel<<<dim3(1024/128, NPTS/128, NB), 256>>>(xc, W2, ut);
        } else {
            gemm_ut_kernel<<<dim3(J2/64, NPTS/64, NB), 256>>>(xc, W2, ut, Cin, J2, L[l].offin);
        }
        gather_kernel<<<dim3(NPTS/8, NB), 256>>>(ut, kn, ymx, ymn, sy, sy2, Cout, J2);
        cudaMemsetAsync(chs, 0, Cout*sizeof(double));
        cudaMemsetAsync(chs2, 0, Cout*sizeof(double));
        colsum_kernel<<<dim3((Cout+255)/256, NB*NPTS/64), 256>>>(sy, sy2, chs, chs2, Cout);
        bnstats_kernel<<<(Cout+255)/256, 256>>>(chs, chs2, gg, bb, scl, shf, Cout,
                                                1.0/((double)NB*NPTS*KNN));
        finalize_kernel<<<dim3(NPTS/32, Cout/32, NB), dim3(32,8)>>>(ymx, ymn, scl, shf,
                                                                    xc, Cout, L[l].offout);
    }

    // w5: h[b][o][n] (reuse dm as h) via 3xTF32 MMA, then BN+lrelu+max monotone trick
    gemm_wx_mma_kernel<<<dim3(NPTS/128, 2048/128, NB), 256>>>(w5, xc, dm);
    cudaMemsetAsync(chs, 0, 2048*sizeof(double));
    cudaMemsetAsync(chs2, 0, 2048*sizeof(double));
    hstats_kernel<<<dim3(2048, NB), 256>>>(dm, chs, chs2, bmx, bmn);
    p_kernel<<<8, 256>>>(chs, chs2, g5, b5, bmx, bmn, pp, cat);

    // head
    fc_kernel<<<2048, 256>>>(w6, wb6, pp, fc, 2048, 2048, 0);
    bnrelu4_kernel<<<8, 256>>>(fc, g6, b6, cat, 2048, 4096, 0);
    fc_kernel<<<4096, 256>>>(w7, wb7, cat, fc, 4096, 4096, 0);
    bnrelu4_kernel<<<16, 256>>>(fc, g7, b7, y7, 4096, 4096, 0);
    fc_kernel<<<400, 256>>>(w8, wb8, y7, (float*)d_out, 4096, 400, 1);
}

// round 17
// speedup vs baseline: 1.7278x; 1.7278x over previous
#include <cuda_runtime.h>
#include <cuda_bf16.h>
#include <math.h>
#include <float.h>

#define NB   4
#define NPTS 2048
#define KNN  20
#define CCAT 963

__device__ __forceinline__ float tf32r(float x){
    float r;
    asm("cvt.rna.tf32.f32 %0, %1;" : "=f"(r) : "f"(x));
    return r;
}

__device__ __forceinline__ void mma_tf32(float& c0, float& c1, float& c2, float& c3,
                                         unsigned a0, unsigned a1, unsigned a2, unsigned a3,
                                         unsigned b0, unsigned b1){
    asm volatile("mma.sync.aligned.m16n8k8.row.col.f32.tf32.tf32.f32 "
                 "{%0,%1,%2,%3}, {%4,%5,%6,%7}, {%8,%9}, {%0,%1,%2,%3};"
                 : "+f"(c0), "+f"(c1), "+f"(c2), "+f"(c3)
                 : "r"(a0), "r"(a1), "r"(a2), "r"(a3), "r"(b0), "r"(b1));
}

// ---------------- scratch (static device globals; no allocation) ----------------
__device__ float  g_xc[(size_t)NB*CCAT*NPTS];          // concat feature buffer (B,963,N)
__device__ float  g_dm[(size_t)NB*NPTS*NPTS];          // distance matrix; reused as h (B,2048,N)
__device__ int    g_knn[NB*NPTS*KNN];
__device__ float  g_w2[1024*256];                      // packed [Wd ; Wc-Wd]
__device__ float  g_ut[(size_t)NB*NPTS*1024];          // (B,N,2*Cout): u then t
__device__ float  g_ymax[(size_t)NB*NPTS*512];
__device__ float  g_ymin[(size_t)NB*NPTS*512];
__device__ float  g_sy [(size_t)NB*NPTS*512];
__device__ float  g_sy2[(size_t)NB*NPTS*512];
__device__ double g_chs[2048];
__device__ double g_chs2[2048];
__device__ float  g_scale[2048];
__device__ float  g_shift[2048];
__device__ float  g_bmax[NB*2048];
__device__ float  g_bmin[NB*2048];
__device__ float  g_p[NB*2048];
__device__ float  g_fc[NB*4096];
__device__ float  g_cat[NB*4096];
__device__ float  g_y7[NB*4096];

// ---------------- kernels ----------------

__global__ void copyx_kernel(const float* __restrict__ x, float* __restrict__ Xc){
    int idx = blockIdx.x*256 + threadIdx.x;
    if (idx >= NB*3*NPTS) return;
    int b = idx/(3*NPTS); int rem = idx%(3*NPTS);
    Xc[(size_t)b*CCAT*NPTS + rem] = x[idx];
}

__global__ void prepw2_kernel(const float* __restrict__ w, float* __restrict__ W2,
                              int Cin, int Cout){
    int idx = blockIdx.x*256 + threadIdx.x;
    int tot = 2*Cout*Cin;
    if (idx >= tot) return;
    int j = idx / Cin, c = idx % Cin;
    if (j < Cout) W2[idx] = w[(size_t)j*(2*Cin) + c];
    else {
        int jj = j - Cout;
        W2[idx] = w[(size_t)jj*(2*Cin) + Cin + c] - w[(size_t)jj*(2*Cin) + c];
    }
}

// D[b][n][m] = sum_c (X[c][n] - X[c][m])^2, symmetric: only upper-tri tile pairs.
// Inner math in packed f32x2 (bitwise identical per element: FADD(a,-b) == FSUB(a,b)).
#define DT 32   // number of 64-wide tiles (2048/64)
__global__ void dist_sym_kernel(const float* __restrict__ Xc, float* __restrict__ D,
                                int C, int coff){
    int b = blockIdx.z;
    int p = blockIdx.x;            // 0 .. DT*(DT+1)/2 - 1
    int bi = 0, accum = 0;
    while (p >= accum + (DT - bi)){ accum += DT - bi; bi++; }
    int bj = bi + (p - accum);
    int n0 = bi*64, m0 = bj*64;

    const float* Xb = Xc + ((size_t)b*CCAT + coff)*NPTS;
    __shared__ float As[16][64];
    __shared__ float Bs[16][64];   // stored NEGATED
    unsigned long long acc2[2][4];
    #pragma unroll
    for (int ip = 0; ip < 2; ip++)
        #pragma unroll
        for (int j = 0; j < 4; j++) acc2[ip][j] = 0ull;

    int t  = threadIdx.x;
    int tx = t & 15, ty = t >> 4;
    for (int c0 = 0; c0 < C; c0 += 16){
        #pragma unroll
        for (int r = 0; r < 4; r++){
            int lin = t + r*256;
            int kc = lin >> 6, i = lin & 63;
            float a = 0.f, bv = 0.f;
            if (c0+kc < C){
                a  = Xb[(size_t)(c0+kc)*NPTS + n0 + i];
                bv = Xb[(size_t)(c0+kc)*NPTS + m0 + i];
            }
            As[kc][i] = a; Bs[kc][i] = -bv;
        }
        __syncthreads();
        #pragma unroll
        for (int kc = 0; kc < 16; kc++){
            float4 aq = *reinterpret_cast<const float4*>(&As[kc][ty*4]);
            float4 bq = *reinterpret_cast<const float4*>(&Bs[kc][tx*4]);  // negated
            unsigned long long ap[2], bd[4];
            asm("mov.b64 %0,{%1,%2};" : "=l"(ap[0]) : "f"(aq.x), "f"(aq.y));
            asm("mov.b64 %0,{%1,%2};" : "=l"(ap[1]) : "f"(aq.z), "f"(aq.w));
            asm("mov.b64 %0,{%1,%1};" : "=l"(bd[0]) : "f"(bq.x));
            asm("mov.b64 %0,{%1,%1};" : "=l"(bd[1]) : "f"(bq.y));
            asm("mov.b64 %0,{%1,%1};" : "=l"(bd[2]) : "f"(bq.z));
            asm("mov.b64 %0,{%1,%1};" : "=l"(bd[3]) : "f"(bq.w));
            #pragma unroll
            for (int ip = 0; ip < 2; ip++)
                #pragma unroll
                for (int j = 0; j < 4; j++){
                    unsigned long long d;
                    asm("add.rn.f32x2 %0, %1, %2;" : "=l"(d) : "l"(ap[ip]), "l"(bd[j]));
                    asm("fma.rn.f32x2 %0, %1, %2, %3;"
                        : "=l"(acc2[ip][j]) : "l"(d), "l"(d), "l"(acc2[ip][j]));
                }
        }
        __syncthreads();
    }
    float accs[4][4];
    #pragma unroll
    for (int ip = 0; ip < 2; ip++)
        #pragma unroll
        for (int j = 0; j < 4; j++)
            asm("mov.b64 {%0,%1}, %2;"
                : "=f"(accs[2*ip][j]), "=f"(accs[2*ip+1][j]) : "l"(acc2[ip][j]));

    float* Db = D + (size_t)b*NPTS*NPTS;
    #pragma unroll
    for (int i = 0; i < 4; i++){
        int n = n0 + ty*4 + i;
        float4 o;
        o.x = accs[i][0]; o.y = accs[i][1]; o.z = accs[i][2]; o.w = accs[i][3];
        *reinterpret_cast<float4*>(&Db[(size_t)n*NPTS + m0 + tx*4]) = o;
    }
    if (bi != bj){
        #pragma unroll
        for (int j = 0; j < 4; j++){
            int m = m0 + tx*4 + j;
            float4 o;
            o.x = accs[0][j]; o.y = accs[1][j]; o.z = accs[2][j]; o.w = accs[3][j];
            *reinterpret_cast<float4*>(&Db[(size_t)m*NPTS + n0 + ty*4]) = o;
        }
    }
}

// Radix-select top-KNN smallest per row (exact; ties -> lowest index).
// Plain smem atomic histogram (round-12 version; match_any variant was 6x slower).
__global__ void topk_kernel(const float* __restrict__ D, int* __restrict__ IDX){
    int b = blockIdx.y, n = blockIdx.x;
    const float* row = D + ((size_t)b*NPTS + n)*NPTS;
    int t = threadIdx.x;

    unsigned v[8];
    #pragma unroll
    for (int j = 0; j < 8; j++)
        v[j] = __float_as_uint(row[t + j*256]);

    __shared__ unsigned hist[256];
    __shared__ unsigned scn[256];
    __shared__ unsigned sh_digit, sh_cntless;
    __shared__ int      outpos, eqcnt;
    __shared__ int      eqlist[2048];

    unsigned prefix = 0;
    int r = KNN;

    #pragma unroll
    for (int pass = 0; pass < 4; pass++){
        int shift = 24 - pass*8;
        hist[t] = 0;
        __syncthreads();
        #pragma unroll
        for (int j = 0; j < 8; j++){
            unsigned x = v[j];
            bool alive = (pass == 0) || ((x >> (shift+8)) == (prefix >> (shift+8)));
            if (alive) atomicAdd(&hist[(x >> shift) & 0xFF], 1u);
        }
        __syncthreads();
        scn[t] = hist[t];
        __syncthreads();
        for (int off = 1; off < 256; off <<= 1){
            unsigned a = (t >= off) ? scn[t-off] : 0u;
            __syncthreads();
            scn[t] += a;
            __syncthreads();
        }
        unsigned prev = (t == 0) ? 0u : scn[t-1];
        if (scn[t] >= (unsigned)r && prev < (unsigned)r){
            sh_digit = (unsigned)t;
            sh_cntless = prev;
        }
        __syncthreads();
        prefix |= sh_digit << shift;
        r -= (int)sh_cntless;
        __syncthreads();
    }

    unsigned T = prefix;
    if (t == 0){ outpos = 0; eqcnt = 0; }
    __syncthreads();

    int base = ((size_t)b*NPTS + n)*KNN;
    #pragma unroll
    for (int j = 0; j < 8; j++){
        unsigned x = v[j];
        int idx = t + j*256;
        if (x < T){
            int p = atomicAdd(&outpos, 1);
            IDX[base + p] = idx;
        } else if (x == T){
            int p = atomicAdd(&eqcnt, 1);
            eqlist[p] = idx;
        }
    }
    __syncthreads();

    if (t < 32){
        int start = KNN - r;
        int ec = eqcnt;
        for (int it = 0; it < r; it++){
            int best = 0x7FFFFFFF;
            for (int i = t; i < ec; i += 32) best = min(best, eqlist[i]);
            #pragma unroll
            for (int o = 16; o > 0; o >>= 1)
                best = min(best, __shfl_xor_sync(0xFFFFFFFF, best, o));
            if (t == 0) IDX[base + start + it] = best;
            for (int i = t; i < ec; i += 32)
                if (eqlist[i] == best) eqlist[i] = 0x7FFFFFFF;
            __syncwarp();
        }
    }
}

// UT[b][n][j] = sum_c W2[j][c] * X[b][c][n]  (exact fp32; layers 1-3 — feeds kNN)
__global__ void gemm_ut_kernel(const float* __restrict__ Xc, const float* __restrict__ W2,
                               float* __restrict__ UT, int Cin, int J2, int coff){
    int b  = blockIdx.z;
    int n0 = blockIdx.y*64, j0 = blockIdx.x*64;
    const float* Xb = Xc + ((size_t)b*CCAT + coff)*NPTS;
    __shared__ float Xs[16][64];
    __shared__ float Ws[16][64];
    float acc[4][4] = {};
    int t = threadIdx.x;
    int tx = t & 15, ty = t >> 4;
    for (int c0 = 0; c0 < Cin; c0 += 16){
        #pragma unroll
        for (int r = 0; r < 4; r++){
            int lin = t + r*256;
            int kc = lin >> 6, i = lin & 63;
            Xs[kc][i] = (c0+kc < Cin) ? Xb[(size_t)(c0+kc)*NPTS + n0 + i] : 0.f;
            int j = lin >> 4, kc2 = lin & 15;
            Ws[kc2][j] = (c0+kc2 < Cin) ? W2[(size_t)(j0+j)*Cin + c0 + kc2] : 0.f;
        }
        __syncthreads();
        #pragma unroll
        for (int kc = 0; kc < 16; kc++){
            float av[4], wv[4];
            #pragma unroll
            for (int i = 0; i < 4; i++){ av[i] = Xs[kc][ty*4+i]; wv[i] = Ws[kc][tx*4+i]; }
            #pragma unroll
            for (int i = 0; i < 4; i++)
                #pragma unroll
                for (int j = 0; j < 4; j++)
                    acc[i][j] += av[i]*wv[j];
        }
        __syncthreads();
    }
    #pragma unroll
    for (int i = 0; i < 4; i++){
        int n = n0 + ty*4 + i;
        float4 o; o.x = acc[i][0]; o.y = acc[i][1]; o.z = acc[i][2]; o.w = acc[i][3];
        *reinterpret_cast<float4*>(&UT[((size_t)b*NPTS + n)*J2 + j0 + tx*4]) = o;
    }
}

// Layer-4 UT via 3xTF32 tensor cores (near-fp32 accuracy).
__global__ void gemm_ut4_mma_kernel(const float* __restrict__ Xc, const float* __restrict__ W2,
                                    float* __restrict__ UT){
    const int Cin = 256, J2 = 1024, coff = 195;
    int b  = blockIdx.z;
    int j0 = blockIdx.x*128, n0 = blockIdx.y*128;
    const float* Xb = Xc + ((size_t)b*CCAT + coff)*NPTS;
    __shared__ float Ahi[128][17], Alo[128][17];   // [n][k]
    __shared__ float Bhi[16][133], Blo[16][133];   // [k][j]
    int t = threadIdx.x;
    int warp = t >> 5, lane = t & 31;
    int g = lane >> 2, tg = lane & 3;
    float acc[4][4][4];
    #pragma unroll
    for (int i=0;i<4;i++)
        #pragma unroll
        for (int j=0;j<4;j++)
            #pragma unroll
            for (int r=0;r<4;r++) acc[i][j][r]=0.f;

    for (int c0 = 0; c0 < Cin; c0 += 16){
        #pragma unroll
        for (int r = 0; r < 8; r++){           // A: 128 n x 16 k
            int lin = t + r*256;
            int k = lin >> 7, i = lin & 127;
            float v = Xb[(size_t)(c0+k)*NPTS + n0 + i];
            float hi = tf32r(v);
            Ahi[i][k] = hi; Alo[i][k] = tf32r(v - hi);
        }
        #pragma unroll
        for (int r = 0; r < 8; r++){           // B: 16 k x 128 j
            int lin = t + r*256;
            int j = lin >> 4, k = lin & 15;
            float v = W2[(size_t)(j0+j)*Cin + c0 + k];
            float hi = tf32r(v);
            Bhi[k][j] = hi; Blo[k][j] = tf32r(v - hi);
        }
        __syncthreads();
        #pragma unroll
        for (int ks = 0; ks < 16; ks += 8){
            unsigned ah[4][4], al[4][4], bh[4][2], bl[4][2];
            #pragma unroll
            for (int i = 0; i < 4; i++){
                int nm = (warp & 1)*64 + i*16;
                ah[i][0] = __float_as_uint(Ahi[nm+g   ][ks+tg  ]);
                ah[i][1] = __float_as_uint(Ahi[nm+g+8 ][ks+tg  ]);
                ah[i][2] = __float_as_uint(Ahi[nm+g   ][ks+tg+4]);
                ah[i][3] = __float_as_uint(Ahi[nm+g+8 ][ks+tg+4]);
                al[i][0] = __float_as_uint(Alo[nm+g   ][ks+tg  ]);
                al[i][1] = __float_as_uint(Alo[nm+g+8 ][ks+tg  ]);
                al[i][2] = __float_as_uint(Alo[nm+g   ][ks+tg+4]);
                al[i][3] = __float_as_uint(Alo[nm+g+8 ][ks+tg+4]);
            }
            #pragma unroll
            for (int j = 0; j < 4; j++){
                int jm = (warp >> 1)*32 + j*8;
                bh[j][0] = __float_as_uint(Bhi[ks+tg  ][jm+g]);
                bh[j][1] = __float_as_uint(Bhi[ks+tg+4][jm+g]);
                bl[j][0] = __float_as_uint(Blo[ks+tg  ][jm+g]);
                bl[j][1] = __float_as_uint(Blo[ks+tg+4][jm+g]);
            }
            #pragma unroll
            for (int i = 0; i < 4; i++)
                #pragma unroll
                for (int j = 0; j < 4; j++){
                    mma_tf32(acc[i][j][0],acc[i][j][1],acc[i][j][2],acc[i][j][3],
                             al[i][0],al[i][1],al[i][2],al[i][3],bh[j][0],bh[j][1]);
                    mma_tf32(acc[i][j][0],acc[i][j][1],acc[i][j][2],acc[i][j][3],
                             ah[i][0],ah[i][1],ah[i][2],ah[i][3],bl[j][0],bl[j][1]);
                    mma_tf32(acc[i][j][0],acc[i][j][1],acc[i][j][2],acc[i][j][3],
                             ah[i][0],ah[i][1],ah[i][2],ah[i][3],bh[j][0],bh[j][1]);
                }
        }
        __syncthreads();
    }
    int wn = n0 + (warp & 1)*64;
    int wj = j0 + (warp >> 1)*32;
    #pragma unroll
    for (int i = 0; i < 4; i++){
        int nrow = wn + i*16;
        #pragma unroll
        for (int j = 0; j < 4; j++){
            int jcol = wj + j*8 + 2*tg;
            float2 v0 = make_float2(acc[i][j][0], acc[i][j][1]);
            float2 v1 = make_float2(acc[i][j][2], acc[i][j][3]);
            *reinterpret_cast<float2*>(&UT[((size_t)b*NPTS + nrow + g    )*J2 + jcol]) = v0;
            *reinterpret_cast<float2*>(&UT[((size_t)b*NPTS + nrow + g + 8)*J2 + jcol]) = v1;
        }
    }
}

// w5 GEMM via 3xTF32 tensor cores: Out[b][o][n] = sum_c W[o][c] * X[b][c][n]
__global__ void gemm_wx_mma_kernel(const float* __restrict__ W, const float* __restrict__ Xc,
                                   float* __restrict__ Out){
    const int C = CCAT, O = 2048;
    int b  = blockIdx.z;
    int o0 = blockIdx.y*128, n0 = blockIdx.x*128;
    const float* Xb = Xc + (size_t)b*CCAT*NPTS;
    __shared__ float Whi[128][17], Wlo[128][17];   // [o][k]
    __shared__ float Xhi[16][132], Xlo[16][132];   // [k][n]
    int t = threadIdx.x;
    int warp = t >> 5, lane = t & 31;
    int g = lane >> 2, tg = lane & 3;
    float acc[4][4][4];
    #pragma unroll
    for (int i=0;i<4;i++)
        #pragma unroll
        for (int j=0;j<4;j++)
            #pragma unroll
            for (int r=0;r<4;r++) acc[i][j][r]=0.f;

    for (int c0 = 0; c0 < C; c0 += 16){
        #pragma unroll
        for (int r = 0; r < 8; r++){           // W: 128 o x 16 k (scalar; stride 963)
            int lin = t + r*256;
            int o = lin >> 4, k = lin & 15;
            float v = (c0+k < C) ? W[(size_t)(o0+o)*C + c0 + k] : 0.f;
            float hi = tf32r(v);
            Whi[o][k] = hi; Wlo[o][k] = tf32r(v - hi);
        }
        #pragma unroll
        for (int r = 0; r < 2; r++){           // X: 16 k x 128 n via float4
            int lin = t + r*256;
            int k = lin >> 5, nq = lin & 31;
            float4 v = make_float4(0.f,0.f,0.f,0.f);
            if (c0+k < C)
                v = *reinterpret_cast<const float4*>(&Xb[(size_t)(c0+k)*NPTS + n0 + nq*4]);
            float4 h, l;
            h.x = tf32r(v.x); l.x = tf32r(v.x - h.x);
            h.y = tf32r(v.y); l.y = tf32r(v.y - h.y);
            h.z = tf32r(v.z); l.z = tf32r(v.z - h.z);
            h.w = tf32r(v.w); l.w = tf32r(v.w - h.w);
            *reinterpret_cast<float4*>(&Xhi[k][nq*4]) = h;
            *reinterpret_cast<float4*>(&Xlo[k][nq*4]) = l;
        }
        __syncthreads();
        #pragma unroll
        for (int ks = 0; ks < 16; ks += 8){
            unsigned ah[4][4], al[4][4], bh[4][2], bl[4][2];
            #pragma unroll
            for (int i = 0; i < 4; i++){
                int om = (warp & 1)*64 + i*16;
                ah[i][0] = __float_as_uint(Whi[om+g   ][ks+tg  ]);
                ah[i][1] = __float_as_uint(Whi[om+g+8 ][ks+tg  ]);
                ah[i][2] = __float_as_uint(Whi[om+g   ][ks+tg+4]);
                ah[i][3] = __float_as_uint(Whi[om+g+8 ][ks+tg+4]);
                al[i][0] = __float_as_uint(Wlo[om+g   ][ks+tg  ]);
                al[i][1] = __float_as_uint(Wlo[om+g+8 ][ks+tg  ]);
                al[i][2] = __float_as_uint(Wlo[om+g   ][ks+tg+4]);
                al[i][3] = __float_as_uint(Wlo[om+g+8 ][ks+tg+4]);
            }
            #pragma unroll
            for (int j = 0; j < 4; j++){
                int nm = (warp >> 1)*32 + j*8;
                bh[j][0] = __float_as_uint(Xhi[ks+tg  ][nm+g]);
                bh[j][1] = __float_as_uint(Xhi[ks+tg+4][nm+g]);
                bl[j][0] = __float_as_uint(Xlo[ks+tg  ][nm+g]);
                bl[j][1] = __float_as_uint(Xlo[ks+tg+4][nm+g]);
            }
            #pragma unroll
            for (int i = 0; i < 4; i++)
                #pragma unroll
                for (int j = 0; j < 4; j++){
                    mma_tf32(acc[i][j][0],acc[i][j][1],acc[i][j][2],acc[i][j][3],
                             al[i][0],al[i][1],al[i][2],al[i][3],bh[j][0],bh[j][1]);
                    mma_tf32(acc[i][j][0],acc[i][j][1],acc[i][j][2],acc[i][j][3],
                             ah[i][0],ah[i][1],ah[i][2],ah[i][3],bl[j][0],bl[j][1]);
                    mma_tf32(acc[i][j][0],acc[i][j][1],acc[i][j][2],acc[i][j][3],
                             ah[i][0],ah[i][1],ah[i][2],ah[i][3],bh[j][0],bh[j][1]);
                }
        }
        __syncthreads();
    }
    int wo = o0 + (warp & 1)*64;
    int wn = n0 + (warp >> 1)*32;
    #pragma unroll
    for (int i = 0; i < 4; i++){
        int orow = wo + i*16;
        #pragma unroll
        for (int j = 0; j < 4; j++){
            int ncol = wn + j*8 + 2*tg;
            float2 v0 = make_float2(acc[i][j][0], acc[i][j][1]);
            float2 v1 = make_float2(acc[i][j][2], acc[i][j][3]);
            *reinterpret_cast<float2*>(&Out[((size_t)b*O + orow + g    )*NPTS + ncol]) = v0;
            *reinterpret_cast<float2*>(&Out[((size_t)b*O + orow + g + 8)*NPTS + ncol]) = v1;
        }
    }
}

// Gather: one warp per point, float4 channel strides. 8 points per 256-thread block.
__global__ void gather_kernel(const float* __restrict__ UT, const int* __restrict__ IDX,
                              float* __restrict__ YMAX, float* __restrict__ YMIN,
                              float* __restrict__ SY, float* __restrict__ SY2,
                              int Cout, int J2){
    int b = blockIdx.y;
    int n0 = blockIdx.x*8;
    int t = threadIdx.x;
    int w = t >> 5, lane = t & 31;
    int n = n0 + w;
    __shared__ int midx[8][KNN];
    if (t < 8*KNN) midx[t/KNN][t%KNN] = IDX[((size_t)b*NPTS + n0 + t/KNN)*KNN + t%KNN];
    __syncthreads();
    const float* utb = UT + (size_t)b*NPTS*J2;
    const float* tr  = utb + (size_t)n*J2 + Cout;
    int nq = Cout >> 2;
    for (int o4 = lane; o4 < nq; o4 += 32){
        int o = o4*4;
        float4 tv = *reinterpret_cast<const float4*>(tr + o);
        float4 mx = make_float4(-FLT_MAX,-FLT_MAX,-FLT_MAX,-FLT_MAX);
        float4 mn = make_float4( FLT_MAX, FLT_MAX, FLT_MAX, FLT_MAX);
        float4 s  = make_float4(0.f,0.f,0.f,0.f);
        float4 s2 = make_float4(0.f,0.f,0.f,0.f);
        #pragma unroll
        for (int k = 0; k < KNN; k++){
            float4 u = *reinterpret_cast<const float4*>(&utb[(size_t)midx[w][k]*J2 + o]);
            float4 y;
            y.x = u.x + tv.x; y.y = u.y + tv.y; y.z = u.z + tv.z; y.w = u.w + tv.w;
            mx.x = fmaxf(mx.x, y.x); mx.y = fmaxf(mx.y, y.y);
            mx.z = fmaxf(mx.z, y.z); mx.w = fmaxf(mx.w, y.w);
            mn.x = fminf(mn.x, y.x); mn.y = fminf(mn.y, y.y);
            mn.z = fminf(mn.z, y.z); mn.w = fminf(mn.w, y.w);
            s.x += y.x; s.y += y.y; s.z += y.z; s.w += y.w;
            s2.x += y.x*y.x; s2.y += y.y*y.y; s2.z += y.z*y.z; s2.w += y.w*y.w;
        }
        size_t oi = ((size_t)(b*NPTS + n))*Cout + o;
        *reinterpret_cast<float4*>(&YMAX[oi]) = mx;
        *reinterpret_cast<float4*>(&YMIN[oi]) = mn;
        *reinterpret_cast<float4*>(&SY[oi])   = s;
        *reinterpret_cast<float4*>(&SY2[oi])  = s2;
    }
}

__global__ void colsum_kernel(const float* __restrict__ SY, const float* __restrict__ SY2,
                              double* __restrict__ CHS, double* __restrict__ CHS2, int Cout){
    int o  = blockIdx.x*256 + threadIdx.x;
    int r0 = blockIdx.y*64;
    if (o >= Cout) return;
    double a = 0.0, a2 = 0.0;
    for (int r = 0; r < 64; r++){
        size_t idx = (size_t)(r0 + r)*Cout + o;
        a += (double)SY[idx]; a2 += (double)SY2[idx];
    }
    atomicAdd(&CHS[o], a);
    atomicAdd(&CHS2[o], a2);
}

__global__ void bnstats_kernel(const double* __restrict__ CHS, const double* __restrict__ CHS2,
                               const float* __restrict__ g, const float* __restrict__ beta,
                               float* __restrict__ scale, float* __restrict__ shift,
                               int C, double invcnt){
    int o = blockIdx.x*256 + threadIdx.x;
    if (o >= C) return;
    double m   = CHS[o]*invcnt;
    double var = CHS2[o]*invcnt - m*m;
    float r   = rsqrtf((float)var + 1e-5f);
    float sc  = g[o]*r;
    scale[o] = sc;
    shift[o] = beta[o] - (float)m*sc;
}

// out = max(f(ymax), f(ymin)), f = lrelu(v*scale+shift); write transposed to (B,C,N)
__global__ void finalize_kernel(const float* __restrict__ YMAX, const float* __restrict__ YMIN,
                                const float* __restrict__ scale, const float* __restrict__ shift,
                                float* __restrict__ Xc, int Cout, int coff){
    int b  = blockIdx.z;
    int n0 = blockIdx.x*32, o0 = blockIdx.y*32;
    __shared__ float s[32][33];
    int tx = threadIdx.x, ty = threadIdx.y;   // 32 x 8
    #pragma unroll
    for (int i = 0; i < 4; i++){
        int n = n0 + ty + i*8, o = o0 + tx;
        size_t idx = ((size_t)(b*NPTS + n))*Cout + o;
        float sc = scale[o], sh = shift[o];
        float v1 = YMAX[idx]*sc + sh; v1 = v1 > 0.f ? v1 : 0.2f*v1;
        float v2 = YMIN[idx]*sc + sh; v2 = v2 > 0.f ? v2 : 0.2f*v2;
        s[tx][ty + i*8] = fmaxf(v1, v2);
    }
    __syncthreads();
    #pragma unroll
    for (int i = 0; i < 4; i++){
        int o = o0 + ty + i*8, n = n0 + tx;
        Xc[((size_t)b*CCAT + coff + o)*NPTS + n] = s[ty + i*8][tx];
    }
}

// per (b,o): sum/sumsq/max/min over n of h  (double accumulation)
__global__ void hstats_kernel(const float* __restrict__ H, double* __restrict__ CHS,
                              double* __restrict__ CHS2, float* __restrict__ BMAX,
                              float* __restrict__ BMIN){
    int b = blockIdx.y, o = blockIdx.x;
    const float* row = H + ((size_t)b*2048 + o)*NPTS;
    int t = threadIdx.x;
    double s = 0.0, s2 = 0.0;
    float mx = -FLT_MAX, mn = FLT_MAX;
    for (int i = t; i < NPTS; i += 256){
        float v = row[i];
        s += (double)v; s2 += (double)v*(double)v;
        mx = fmaxf(mx, v); mn = fminf(mn, v);
    }
    __shared__ double rs[256], rs2[256];
    __shared__ float rmx[256], rmn[256];
    rs[t] = s; rs2[t] = s2; rmx[t] = mx; rmn[t] = mn;
    __syncthreads();
    for (int st = 128; st > 0; st >>= 1){
        if (t < st){
            rs[t] += rs[t+st]; rs2[t] += rs2[t+st];
            rmx[t] = fmaxf(rmx[t], rmx[t+st]); rmn[t] = fminf(rmn[t], rmn[t+st]);
        }
        __syncthreads();
    }
    if (t == 0){
        atomicAdd(&CHS[o], rs[0]);
        atomicAdd(&CHS2[o], rs2[0]);
        BMAX[b*2048 + o] = rmx[0];
        BMIN[b*2048 + o] = rmn[0];
    }
}

__global__ void p_kernel(const double* __restrict__ CHS, const double* __restrict__ CHS2,
                         const float* __restrict__ g5, const float* __restrict__ b5,
                         const float* __restrict__ BMAX, const float* __restrict__ BMIN,
                         float* __restrict__ P, float* __restrict__ CAT){
    int o = blockIdx.x*256 + threadIdx.x;
    if (o >= 2048) return;
    double invcnt = 1.0/((double)NB*NPTS);
    double m = CHS[o]*invcnt;
    double var = CHS2[o]*invcnt - m*m;
    float sc = g5[o]*rsqrtf((float)var + 1e-5f);
    float sh = b5[o] - (float)m*sc;
    for (int b = 0; b < NB; b++){
        float v1 = BMAX[b*2048+o]*sc + sh; v1 = v1 > 0.f ? v1 : 0.2f*v1;
        float v2 = BMIN[b*2048+o]*sc + sh; v2 = v2 > 0.f ? v2 : 0.2f*v2;
        float v = fmaxf(v1, v2);
        P[b*2048 + o] = v;
        CAT[b*4096 + 2048 + o] = v;
    }
}

// OUT[b][o] = sum_c W[o][c]*IN[b][c] + bias[o], optional tanh
__global__ void fc_kernel(const float* __restrict__ W, const float* __restrict__ bias,
                          const float* __restrict__ IN, float* __restrict__ OUT,
                          int Cin, int O, int do_tanh){
    int o = blockIdx.x, t = threadIdx.x;
    const float* wr = W + (size_t)o*Cin;
    float a0 = 0.f, a1 = 0.f, a2 = 0.f, a3 = 0.f;
    for (int c = t; c < Cin; c += 256){
        float wv = wr[c];
        a0 += wv*IN[c];
        a1 += wv*IN[Cin + c];
        a2 += wv*IN[2*Cin + c];
        a3 += wv*IN[3*Cin + c];
    }
    __shared__ float red[4][256];
    red[0][t] = a0; red[1][t] = a1; red[2][t] = a2; red[3][t] = a3;
    __syncthreads();
    for (int s = 128; s > 0; s >>= 1){
        if (t < s){
            red[0][t] += red[0][t+s]; red[1][t] += red[1][t+s];
            red[2][t] += red[2][t+s]; red[3][t] += red[3][t+s];
        }
        __syncthreads();
    }
    if (t == 0){
        float bv = bias[o];
        for (int b = 0; b < NB; b++){
            float v = red[b][0] + bv;
            if (do_tanh) v = tanhf(v);
            OUT[(size_t)b*O + o] = v;
        }
    }
}

// batch-of-4 BN + relu (L=1 case)
__global__ void bnrelu4_kernel(const float* __restrict__ Y, const float* __restrict__ g,
                               const float* __restrict__ beta, float* __restrict__ OUT,
                               int C, int outStride, int outOff){
    int o = blockIdx.x*256 + threadIdx.x;
    if (o >= C) return;
    float m = 0.f;
    #pragma unroll
    for (int b = 0; b < NB; b++) m += Y[(size_t)b*C + o];
    m *= 0.25f;
    float var = 0.f;
    #pragma unroll
    for (int b = 0; b < NB; b++){ float d = Y[(size_t)b*C + o] - m; var += d*d; }
    var *= 0.25f;
    float sc = g[o]*rsqrtf(var + 1e-5f);
    float sh = beta[o] - m*sc;
    #pragma unroll
    for (int b = 0; b < NB; b++){
        float v = Y[(size_t)b*C + o]*sc + sh;
        OUT[(size_t)b*outStride + outOff + o] = fmaxf(v, 0.f);
    }
}

// ---------------- host orchestration ----------------
extern "C" void kernel_launch(void* const* d_in, const int* in_sizes, int n_in,
                              void* d_out, int out_size){
    (void)in_sizes; (void)n_in; (void)out_size;
    const float* x   = (const float*)d_in[0];
    const float* w5  = (const float*)d_in[13];
    const float* g5  = (const float*)d_in[14];
    const float* b5  = (const float*)d_in[15];
    const float* w6  = (const float*)d_in[16];
    const float* wb6 = (const float*)d_in[17];
    const float* g6  = (const float*)d_in[18];
    const float* b6  = (const float*)d_in[19];
    const float* w7  = (const float*)d_in[20];
    const float* wb7 = (const float*)d_in[21];
    const float* g7  = (const float*)d_in[22];
    const float* b7  = (const float*)d_in[23];
    const float* w8  = (const float*)d_in[24];
    const float* wb8 = (const float*)d_in[25];

    void *p_xc, *p_dm, *p_knn, *p_w2, *p_ut, *p_ymax, *p_ymin, *p_sy, *p_sy2;
    void *p_chs, *p_chs2, *p_scale, *p_shift, *p_bmax, *p_bmin, *p_p, *p_fc, *p_cat, *p_y7;
    cudaGetSymbolAddress(&p_xc, g_xc);
    cudaGetSymbolAddress(&p_dm, g_dm);       cudaGetSymbolAddress(&p_knn, g_knn);
    cudaGetSymbolAddress(&p_w2, g_w2);       cudaGetSymbolAddress(&p_ut, g_ut);
    cudaGetSymbolAddress(&p_ymax, g_ymax);   cudaGetSymbolAddress(&p_ymin, g_ymin);
    cudaGetSymbolAddress(&p_sy, g_sy);       cudaGetSymbolAddress(&p_sy2, g_sy2);
    cudaGetSymbolAddress(&p_chs, g_chs);     cudaGetSymbolAddress(&p_chs2, g_chs2);
    cudaGetSymbolAddress(&p_scale, g_scale); cudaGetSymbolAddress(&p_shift, g_shift);
    cudaGetSymbolAddress(&p_bmax, g_bmax);   cudaGetSymbolAddress(&p_bmin, g_bmin);
    cudaGetSymbolAddress(&p_p, g_p);         cudaGetSymbolAddress(&p_fc, g_fc);
    cudaGetSymbolAddress(&p_cat, g_cat);     cudaGetSymbolAddress(&p_y7, g_y7);

    float* xc  = (float*)p_xc;
    float* dm  = (float*)p_dm;   int*   kn  = (int*)p_knn;
    float* W2  = (float*)p_w2;   float* ut  = (float*)p_ut;
    float* ymx = (float*)p_ymax; float* ymn = (float*)p_ymin;
    float* sy  = (float*)p_sy;   float* sy2 = (float*)p_sy2;
    double* chs = (double*)p_chs;double* chs2= (double*)p_chs2;
    float* scl = (float*)p_scale;float* shf = (float*)p_shift;
    float* bmx = (float*)p_bmax; float* bmn = (float*)p_bmin;
    float* pp  = (float*)p_p;    float* fc  = (float*)p_fc;
    float* cat = (float*)p_cat;  float* y7  = (float*)p_y7;

    copyx_kernel<<<(NB*3*NPTS + 255)/256, 256>>>(x, xc);

    struct LCfg { int cin, cout, offin, offout, wi, gi, bi; };
    const LCfg L[4] = {
        {  3,  64,   0,   3,  1,  2,  3},
        { 64, 128,   3,  67,  4,  5,  6},
        {128, 256,  67, 195,  7,  8,  9},
        {256, 512, 195, 451, 10, 11, 12},
    };

    const int NPAIR = DT*(DT+1)/2;   // 528

    for (int l = 0; l < 4; l++){
        const float* w  = (const float*)d_in[L[l].wi];
        const float* gg = (const float*)d_in[L[l].gi];
        const float* bb = (const float*)d_in[L[l].bi];
        int Cin = L[l].cin, Cout = L[l].cout, J2 = 2*Cout;

        prepw2_kernel<<<(2*Cout*Cin + 255)/256, 256>>>(w, W2, Cin, Cout);
        dist_sym_kernel<<<dim3(NPAIR, 1, NB), 256>>>(xc, dm, Cin, L[l].offin);
        topk_kernel<<<dim3(NPTS, NB), 256>>>(dm, kn);
        if (l == 3){
            gemm_ut4_mma_kernel<<<dim3(1024/128, NPTS/128, NB), 256>>>(xc, W2, ut);
        } else {
            gemm_ut_kernel<<<dim3(J2/64, NPTS/64, NB), 256>>>(xc, W2, ut, Cin, J2, L[l].offin);
        }
        gather_kernel<<<dim3(NPTS/8, NB), 256>>>(ut, kn, ymx, ymn, sy, sy2, Cout, J2);
        cudaMemsetAsync(chs, 0, Cout*sizeof(double));
        cudaMemsetAsync(chs2, 0, Cout*sizeof(double));
        colsum_kernel<<<dim3((Cout+255)/256, NB*NPTS/64), 256>>>(sy, sy2, chs, chs2, Cout);
        bnstats_kernel<<<(Cout+255)/256, 256>>>(chs, chs2, gg, bb, scl, shf, Cout,
                                                1.0/((double)NB*NPTS*KNN));
        finalize_kernel<<<dim3(NPTS/32, Cout/32, NB), dim3(32,8)>>>(ymx, ymn, scl, shf,
                                                                    xc, Cout, L[l].offout);
    }

    // w5: h[b][o][n] (reuse dm as h) via 3xTF32 MMA, then BN+lrelu+max monotone trick
    gemm_wx_mma_kernel<<<dim3(NPTS/128, 2048/128, NB), 256>>>(w5, xc, dm);
    cudaMemsetAsync(chs, 0, 2048*sizeof(double));
    cudaMemsetAsync(chs2, 0, 2048*sizeof(double));
    hstats_kernel<<<dim3(2048, NB), 256>>>(dm, chs, chs2, bmx, bmn);
    p_kernel<<<8, 256>>>(chs, chs2, g5, b5, bmx, bmn, pp, cat);

    // head
    fc_kernel<<<2048, 256>>>(w6, wb6, pp, fc, 2048, 2048, 0);
    bnrelu4_kernel<<<8, 256>>>(fc, g6, b6, cat, 2048, 4096, 0);
    fc_kernel<<<4096, 256>>>(w7, wb7, cat, fc, 4096, 4096, 0);
    bnrelu4_kernel<<<16, 256>>>(fc, g7, b7, y7, 4096, 4096, 0);
    fc_kernel<<<400, 256>>>(w8, wb8, y7, (float*)d_out, 4096, 400, 1);
}